// round 11
// baseline (speedup 1.0000x reference)
#include <cuda_runtime.h>
#include <cstdint>

#define THREADS 256

// ---- smem u32 layout (per CTA; 2 CTAs/SM) ----
#define KP2 24                        // K/Q row stride (u32); conflict-free LDS.64 frag reads
#define VP2 280                       // V row stride (u32); conflict-free LDS.64
#define OFF_K 0                       // u32[512*KP2]  K f16x2 pairs along d
#define OFF_V (512*KP2)               // u32[32*VP2]   V f16x2 pairs along key
#define OFF_W (OFF_V + 32*VP2)        // f32[288] transposed [tap][d]
#define OFF_B (OFF_W + 288)           // f32[32]
#define OFF_Q (OFF_B + 32)            // u32[256*KP2]  Q f16x2 pairs along d (this CTA's rows)
#define SMEM_WORDS (OFF_Q + 256*KP2)
#define SMEM_BYTES (SMEM_WORDS*4)     // ~110.8 KB -> 2 CTAs still co-resident (228KB pool)
// epilogue aliases (dead K/V region):
#define OFF_OB 0                      // f32[256*36]  normalized O staging
#define OFF_VF (256*36)               // f32[272*36]  fp32 V conv tile (ends 19008 < OFF_W)

__device__ __forceinline__ uint16_t f16_of(float f){
    uint16_t u; asm("cvt.rn.f16.f32 %0, %1;" : "=h"(u) : "f"(f)); return u;
}
__device__ __forceinline__ uint32_t pack16(uint16_t lo, uint16_t hi){
    uint32_t d; asm("mov.b32 %0, {%1, %2};" : "=r"(d) : "h"(lo), "h"(hi)); return d;
}
__device__ __forceinline__ uint32_t packf16x2(float lo, float hi){
    uint32_t d; asm("cvt.rn.f16x2.f32 %0, %1, %2;" : "=r"(d) : "f"(hi), "f"(lo)); return d;
}
__device__ __forceinline__ uint32_t ex2_f16x2(uint32_t x){
    uint32_t r; asm("ex2.approx.f16x2 %0, %1;" : "=r"(r) : "r"(x)); return r;
}
// fp32-accum mma (PV + L)
__device__ __forceinline__ void mma16(float* c, uint32_t a0,uint32_t a1,uint32_t a2,uint32_t a3,
                                      uint32_t b0,uint32_t b1){
    asm("mma.sync.aligned.m16n8k16.row.col.f32.f16.f16.f32 "
        "{%0,%1,%2,%3},{%4,%5,%6,%7},{%8,%9},{%0,%1,%2,%3};"
        : "+f"(c[0]),"+f"(c[1]),"+f"(c[2]),"+f"(c[3])
        : "r"(a0),"r"(a1),"r"(a2),"r"(a3),"r"(b0),"r"(b1));
}
// f16-accum mma (QK)
__device__ __forceinline__ void mma16h(uint32_t* c, uint32_t a0,uint32_t a1,uint32_t a2,uint32_t a3,
                                       uint32_t b0,uint32_t b1){
    asm("mma.sync.aligned.m16n8k16.row.col.f16.f16.f16.f16 "
        "{%0,%1},{%2,%3,%4,%5},{%6,%7},{%0,%1};"
        : "+r"(c[0]),"+r"(c[1])
        : "r"(a0),"r"(a1),"r"(a2),"r"(a3),"r"(b0),"r"(b1));
}
// word position within a 16-word row for logical d-pair dp (pairs (j, j+4) interleaved)
__device__ __forceinline__ int wordpos(int dp){
    return (dp & 8) + ((dp & 3) << 1) + ((dp >> 2) & 1);
}

// 2 CTAs per (window, head); each CTA owns 256 query rows, holds full K/V.
__global__ void __launch_bounds__(THREADS, 2)
cswin_attn_f16v8(const float* __restrict__ temp,
                 const float* __restrict__ conv_w,
                 const float* __restrict__ conv_b,
                 float* __restrict__ out)
{
    extern __shared__ uint32_t smw[];
    float* sWt = (float*)(smw + OFF_W);
    float* sB  = (float*)(smw + OFF_B);
    float* Ob  = (float*)(smw + OFF_OB);
    float* sVf = (float*)(smw + OFF_VF);

    const int tid  = threadIdx.x;
    const int lane = tid & 31;
    const int warp = tid >> 5;
    const int g4   = lane >> 2;
    const int t4   = lane & 3;
    const int grp  = lane >> 2;          // lane quad, for fill rotation

    const int bid   = blockIdx.x;
    const int half  = bid & 1;
    const int whead = bid >> 1;
    const int head  = whead & 3;
    const int w     = whead >> 2;
    const int b     = w >> 3;
    const int nw    = w & 7;

    const size_t planeStride = 128ull * 4096ull;
    const float* qp = temp + ((size_t)b*3 + 0)*planeStride + (size_t)(head*32)*4096 + nw*8;
    const float* kp = temp + ((size_t)b*3 + 1)*planeStride + (size_t)(head*32)*4096 + nw*8;
    const float* vp = temp + ((size_t)b*3 + 2)*planeStride + (size_t)(head*32)*4096 + nw*8;

    // ---- K fill: thread owns even key pair; lane-quad-rotated d order.
    //      LDG stays coalesced (4-lane groups read one 32B run per plane);
    //      STS spreads across banks (2-way instead of 16-way). ----
    {
        const int key0 = 2*tid;
        const int so = (key0 >> 3)*64 + (key0 & 7);
        #pragma unroll
        for (int s = 0; s < 16; ++s) {
            const int dp = (s + grp) & 15;
            const int d0 = 2*dp;
            float2 v0 = *reinterpret_cast<const float2*>(kp + (size_t)d0*4096 + so);
            float2 v1 = *reinterpret_cast<const float2*>(kp + (size_t)(d0+1)*4096 + so);
            const int wp = wordpos(dp);
            smw[OFF_K + key0*KP2 + wp]     = pack16(f16_of(v0.x), f16_of(v1.x));
            smw[OFF_K + (key0+1)*KP2 + wp] = pack16(f16_of(v0.y), f16_of(v1.y));
        }
    }
    // ---- Q fill: thread owns one row; rotated like K; scale folded ----
    const float qscale = 0.17677669529663687f * 1.4426950408889634f; // 32^-0.5 * log2(e)
    {
        const int row = tid;                    // local row
        const int grow = half*256 + row;
        const int so = (grow >> 3)*64 + (grow & 7);
        #pragma unroll
        for (int s = 0; s < 16; ++s) {
            const int dp = (s + grp) & 15;
            const int d0 = 2*dp;
            float f0 = qp[(size_t)d0*4096 + so] * qscale;
            float f1 = qp[(size_t)(d0+1)*4096 + so] * qscale;
            smw[OFF_Q + row*KP2 + wordpos(dp)] = pack16(f16_of(f0), f16_of(f1));
        }
    }
    // ---- V fill: f16 pairs along key, (t4, t4+4) word-interleaved ----
    for (int i = tid; i < 32*256; i += THREADS) {
        const int d = i >> 8, kpi = i & 255;
        const int t = kpi & 7, m = kpi >> 3;
        const int word = m*8 + ((t < 4) ? 2*t : 2*(t-4) + 1);
        const int key0 = 2*kpi;
        const int so = (key0 >> 3)*64 + (key0 & 7);
        float2 v = *reinterpret_cast<const float2*>(vp + (size_t)d*4096 + so);
        smw[OFF_V + d*VP2 + word] = packf16x2(v.x, v.y);
    }
    for (int i = tid; i < 288; i += THREADS) {
        const int d = i / 9, widx = i % 9;
        sWt[widx*32 + d] = conv_w[head*288 + i];
    }
    if (tid < 32) sB[tid] = conv_b[head*32 + tid];

    float O[2][4][4];
    float Lacc[2][4];
    #pragma unroll
    for (int mt = 0; mt < 2; ++mt) {
        #pragma unroll
        for (int e = 0; e < 4; ++e) Lacc[mt][e] = 0.f;
        #pragma unroll
        for (int nt = 0; nt < 4; ++nt)
            #pragma unroll
            for (int e = 0; e < 4; ++e) O[mt][nt][e] = 0.f;
    }
    const uint32_t ONES = 0x3C003C00u;
    const int rwl = warp * 32;

    __syncthreads();

    // ---- Q fragments once from smem (8x LDS.64, conflict-free) ----
    uint32_t Qh[2][2][4];
    #pragma unroll
    for (int mt = 0; mt < 2; ++mt)
        #pragma unroll
        for (int ch = 0; ch < 2; ++ch) {
            const int r0 = rwl + mt*16 + g4;
            uint2 lo = *reinterpret_cast<const uint2*>(smw + OFF_Q + r0*KP2 + ch*8 + 2*t4);
            uint2 hi = *reinterpret_cast<const uint2*>(smw + OFF_Q + (r0+8)*KP2 + ch*8 + 2*t4);
            Qh[mt][ch][0] = lo.x;   // row g4,   d-lo
            Qh[mt][ch][1] = hi.x;   // row g4+8, d-lo
            Qh[mt][ch][2] = lo.y;   // row g4,   d-hi
            Qh[mt][ch][3] = hi.y;   // row g4+8, d-hi
        }

    // ================= mainloop: 16 tiles of 32 keys =================
    #pragma unroll 1
    for (int kbl = 0; kbl < 512; kbl += 32) {
        uint2 Bk[2][4];
        #pragma unroll
        for (int ch = 0; ch < 2; ++ch)
            #pragma unroll
            for (int nt = 0; nt < 4; ++nt) {
                const int key = kbl + nt*8 + g4;
                Bk[ch][nt] = *reinterpret_cast<const uint2*>(
                    smw + OFF_K + key*KP2 + ch*8 + 2*t4);
            }

        // ---- S = Q K^T : f16 accumulate, D packed f16x2 ----
        uint32_t Sh[2][4][2];
        #pragma unroll
        for (int mt = 0; mt < 2; ++mt)
            #pragma unroll
            for (int nt = 0; nt < 4; ++nt) { Sh[mt][nt][0] = 0u; Sh[mt][nt][1] = 0u; }

        #pragma unroll
        for (int ch = 0; ch < 2; ++ch)
            #pragma unroll
            for (int nt = 0; nt < 4; ++nt)
                #pragma unroll
                for (int mt = 0; mt < 2; ++mt)
                    mma16h(Sh[mt][nt], Qh[mt][ch][0],Qh[mt][ch][1],Qh[mt][ch][2],Qh[mt][ch][3],
                           Bk[ch][nt].x, Bk[ch][nt].y);

        uint2 Bv[2][4];
        #pragma unroll
        for (int chk = 0; chk < 2; ++chk)
            #pragma unroll
            for (int ntd = 0; ntd < 4; ++ntd) {
                const int d = ntd*8 + g4;
                Bv[chk][ntd] = *reinterpret_cast<const uint2*>(
                    smw + OFF_V + d*VP2 + (kbl >> 1) + chk*8 + 2*t4);
            }

        // ---- softmax numerators (shift-free) on packed f16x2 S ----
        uint32_t P[2][4][2];
        #pragma unroll
        for (int mt = 0; mt < 2; ++mt)
            #pragma unroll
            for (int nt = 0; nt < 4; ++nt) {
                P[mt][nt][0] = ex2_f16x2(Sh[mt][nt][0]);
                P[mt][nt][1] = ex2_f16x2(Sh[mt][nt][1]);
            }

        // ---- L += P @ ones ----
        #pragma unroll
        for (int chk = 0; chk < 2; ++chk)
            #pragma unroll
            for (int mt = 0; mt < 2; ++mt)
                mma16(Lacc[mt],
                      P[mt][2*chk][0],   P[mt][2*chk][1],
                      P[mt][2*chk+1][0], P[mt][2*chk+1][1],
                      ONES, ONES);

        // ---- O += P V ----
        #pragma unroll
        for (int chk = 0; chk < 2; ++chk)
            #pragma unroll
            for (int ntd = 0; ntd < 4; ++ntd)
                #pragma unroll
                for (int mt = 0; mt < 2; ++mt)
                    mma16(O[mt][ntd],
                          P[mt][2*chk][0],   P[mt][2*chk][1],
                          P[mt][2*chk+1][0], P[mt][2*chk+1][1],
                          Bv[chk][ntd].x, Bv[chk][ntd].y);
    }

    // ---- normalize; repurpose dead K/V smem for Ob + fp32 conv tile ----
    float inv0[2], inv1[2];
    #pragma unroll
    for (int mt = 0; mt < 2; ++mt) {
        inv0[mt] = 1.0f / Lacc[mt][0];
        inv1[mt] = 1.0f / Lacc[mt][2];
    }
    __syncthreads();   // mainloop smem reads complete

    #pragma unroll
    for (int mt = 0; mt < 2; ++mt) {
        const int r = rwl + mt*16 + g4;
        #pragma unroll
        for (int ntd = 0; ntd < 4; ++ntd) {
            const int dd = ntd*8 + 2*t4;
            Ob[r*36 + dd]        = O[mt][ntd][0] * inv0[mt];
            Ob[r*36 + dd + 1]    = O[mt][ntd][1] * inv0[mt];
            Ob[(r+8)*36 + dd]    = O[mt][ntd][2] * inv1[mt];
            Ob[(r+8)*36 + dd +1] = O[mt][ntd][3] * inv1[mt];
        }
    }

    // ---- fill fp32 V conv tile: 34 halo h-rows x 8 w x 32 d, coalesced float4 ----
    const int hstart = half*32 - 1;
    for (int e = tid; e < 34*64; e += THREADS) {
        const int hl  = e >> 6;
        const int rem = e & 63;
        const int d   = rem >> 1;
        const int q   = (rem & 1) * 4;
        const int hh  = hstart + hl;
        if (hh >= 0 && hh < 64) {
            float4 v = *reinterpret_cast<const float4*>(vp + (size_t)d*4096 + hh*64 + q);
            sVf[(hl*8 + q + 0)*36 + d] = v.x;
            sVf[(hl*8 + q + 1)*36 + d] = v.y;
            sVf[(hl*8 + q + 2)*36 + d] = v.z;
            sVf[(hl*8 + q + 3)*36 + d] = v.w;
        }
    }
    __syncthreads();

    // ---- fused rpe depthwise 3x3 from smem (exact fp32) + store ----
    {
        const int lg = half*256 + tid;
        const int h = lg >> 3, wsp = lg & 7;
        float o[32];
        const float4* ob4 = reinterpret_cast<const float4*>(Ob + tid*36);
        #pragma unroll
        for (int i = 0; i < 8; ++i) {
            float4 v = ob4[i];
            o[4*i] = v.x; o[4*i+1] = v.y; o[4*i+2] = v.z; o[4*i+3] = v.w;
        }

        #pragma unroll
        for (int kh = 0; kh < 3; ++kh) {
            const int hh = h + kh - 1;
            if (hh < 0 || hh >= 64) continue;
            const int hl = hh - hstart;
            #pragma unroll
            for (int kw = 0; kw < 3; ++kw) {
                const int ww = wsp + kw - 1;
                if (ww < 0 || ww >= 8) continue;
                const float4* v4 = reinterpret_cast<const float4*>(sVf + (hl*8 + ww)*36);
                const float4* w4 = reinterpret_cast<const float4*>(sWt + (kh*3 + kw)*32);
                #pragma unroll
                for (int i = 0; i < 8; ++i) {
                    float4 vv = v4[i], wv = w4[i];
                    o[4*i]   += wv.x * vv.x;
                    o[4*i+1] += wv.y * vv.y;
                    o[4*i+2] += wv.z * vv.z;
                    o[4*i+3] += wv.w * vv.w;
                }
            }
        }
        #pragma unroll
        for (int d = 0; d < 32; ++d) o[d] += sB[d];

        float4* orow = reinterpret_cast<float4*>(
            out + ((size_t)(b*4096 + h*64 + nw*8 + wsp))*128 + head*32);
        #pragma unroll
        for (int i = 0; i < 8; ++i)
            orow[i] = make_float4(o[4*i], o[4*i+1], o[4*i+2], o[4*i+3]);
    }
}

extern "C" void kernel_launch(void* const* d_in, const int* in_sizes, int n_in,
                              void* d_out, int out_size)
{
    const float* temp   = (const float*)d_in[0];
    const float* conv_w = (const float*)d_in[1];
    const float* conv_b = (const float*)d_in[2];
    float* out = (float*)d_out;

    cudaFuncSetAttribute(cswin_attn_f16v8,
                         cudaFuncAttributeMaxDynamicSharedMemorySize, SMEM_BYTES);
    cswin_attn_f16v8<<<1024, THREADS, SMEM_BYTES>>>(temp, conv_w, conv_b, out);
}

// round 12
// speedup vs baseline: 1.3058x; 1.3058x over previous
#include <cuda_runtime.h>
#include <cstdint>

#define THREADS 256

// ---- smem u32 layout (per CTA; 2 CTAs/SM) ----
#define KP2 24                        // K row stride (u32); conflict-free LDS.64
#define VP2 280                       // V row stride (u32); conflict-free LDS.64
#define OFF_K 0                       // u32[512*KP2]  K f16x2 pairs along d
#define OFF_V (512*KP2)               // u32[32*VP2]   V f16x2 pairs along key
#define OFF_W (OFF_V + 32*VP2)        // f32[288] transposed [tap][d]
#define OFF_B (OFF_W + 288)           // f32[32]
#define SMEM_WORDS (OFF_B + 32)
#define SMEM_BYTES (SMEM_WORDS*4)     // ~86.3 KB -> 2 CTAs co-resident, L1D ~56KB preserved
// epilogue aliases (dead K/V region):
#define OFF_OB 0                      // f32[256*36]  normalized O staging
#define OFF_VF (256*36)               // f32[272*36]  fp32 V conv tile (34 h x 8 w rows)

__device__ __forceinline__ uint16_t f16_of(float f){
    uint16_t u; asm("cvt.rn.f16.f32 %0, %1;" : "=h"(u) : "f"(f)); return u;
}
__device__ __forceinline__ uint32_t pack16(uint16_t lo, uint16_t hi){
    uint32_t d; asm("mov.b32 %0, {%1, %2};" : "=r"(d) : "h"(lo), "h"(hi)); return d;
}
__device__ __forceinline__ uint32_t packf16x2(float lo, float hi){
    uint32_t d; asm("cvt.rn.f16x2.f32 %0, %1, %2;" : "=r"(d) : "f"(hi), "f"(lo)); return d;
}
__device__ __forceinline__ uint32_t ex2_f16x2(uint32_t x){
    uint32_t r; asm("ex2.approx.f16x2 %0, %1;" : "=r"(r) : "r"(x)); return r;
}
// fp32-accum mma (PV + L)
__device__ __forceinline__ void mma16(float* c, uint32_t a0,uint32_t a1,uint32_t a2,uint32_t a3,
                                      uint32_t b0,uint32_t b1){
    asm("mma.sync.aligned.m16n8k16.row.col.f32.f16.f16.f32 "
        "{%0,%1,%2,%3},{%4,%5,%6,%7},{%8,%9},{%0,%1,%2,%3};"
        : "+f"(c[0]),"+f"(c[1]),"+f"(c[2]),"+f"(c[3])
        : "r"(a0),"r"(a1),"r"(a2),"r"(a3),"r"(b0),"r"(b1));
}
// f16-accum mma (QK): D = 2x f16x2 regs, (c0,c1) row g4 / (c2,c3) row g4+8
__device__ __forceinline__ void mma16h(uint32_t* c, uint32_t a0,uint32_t a1,uint32_t a2,uint32_t a3,
                                       uint32_t b0,uint32_t b1){
    asm("mma.sync.aligned.m16n8k16.row.col.f16.f16.f16.f16 "
        "{%0,%1},{%2,%3,%4,%5},{%6,%7},{%0,%1};"
        : "+r"(c[0]),"+r"(c[1])
        : "r"(a0),"r"(a1),"r"(a2),"r"(a3),"r"(b0),"r"(b1));
}
// word position within a 16-word row for logical d-pair dp (pairs (j, j+4) interleaved)
__device__ __forceinline__ int wordpos(int dp){
    return (dp & 8) + ((dp & 3) << 1) + ((dp >> 2) & 1);
}

// 2 CTAs per (window, head); each CTA owns 256 query rows, holds full K/V.
__global__ void __launch_bounds__(THREADS, 2)
cswin_attn_f16v9(const float* __restrict__ temp,
                 const float* __restrict__ conv_w,
                 const float* __restrict__ conv_b,
                 float* __restrict__ out)
{
    extern __shared__ uint32_t smw[];
    float* sWt = (float*)(smw + OFF_W);
    float* sB  = (float*)(smw + OFF_B);
    float* Ob  = (float*)(smw + OFF_OB);
    float* sVf = (float*)(smw + OFF_VF);

    const int tid  = threadIdx.x;
    const int lane = tid & 31;
    const int warp = tid >> 5;
    const int g4   = lane >> 2;
    const int t4   = lane & 3;

    const int bid   = blockIdx.x;
    const int half  = bid & 1;
    const int whead = bid >> 1;
    const int head  = whead & 3;
    const int w     = whead >> 2;
    const int b     = w >> 3;
    const int nw    = w & 7;

    const size_t planeStride = 128ull * 4096ull;
    const float* qp = temp + ((size_t)b*3 + 0)*planeStride + (size_t)(head*32)*4096 + nw*8;
    const float* kp = temp + ((size_t)b*3 + 1)*planeStride + (size_t)(head*32)*4096 + nw*8;
    const float* vp = temp + ((size_t)b*3 + 2)*planeStride + (size_t)(head*32)*4096 + nw*8;

    // ---- K fill: thread owns even key pair; lane-quad-rotated d order.
    //      LDG per-quad coalescing unchanged; STS bank conflicts 16-way -> ~2-way. ----
    {
        const int key0 = 2*tid;
        const int so = (key0 >> 3)*64 + (key0 & 7);
        #pragma unroll
        for (int s = 0; s < 16; ++s) {
            const int dp = (s + g4) & 15;
            const int d0 = 2*dp;
            float2 v0 = *reinterpret_cast<const float2*>(kp + (size_t)d0*4096 + so);
            float2 v1 = *reinterpret_cast<const float2*>(kp + (size_t)(d0+1)*4096 + so);
            const int wp = wordpos(dp);
            smw[OFF_K + key0*KP2 + wp]     = pack16(f16_of(v0.x), f16_of(v1.x));
            smw[OFF_K + (key0+1)*KP2 + wp] = pack16(f16_of(v0.y), f16_of(v1.y));
        }
    }
    // ---- V fill: f16 pairs along key, (t4, t4+4) word-interleaved ----
    for (int i = tid; i < 32*256; i += THREADS) {
        const int d = i >> 8, kpi = i & 255;
        const int t = kpi & 7, m = kpi >> 3;
        const int word = m*8 + ((t < 4) ? 2*t : 2*(t-4) + 1);
        const int key0 = 2*kpi;
        const int so = (key0 >> 3)*64 + (key0 & 7);
        float2 v = *reinterpret_cast<const float2*>(vp + (size_t)d*4096 + so);
        smw[OFF_V + d*VP2 + word] = packf16x2(v.x, v.y);
    }
    for (int i = tid; i < 288; i += THREADS) {
        const int d = i / 9, widx = i % 9;
        sWt[widx*32 + d] = conv_w[head*288 + i];
    }
    if (tid < 32) sB[tid] = conv_b[head*32 + tid];

    // ---- Q fragments -> registers (single f16, scale folded) ----
    const float qscale = 0.17677669529663687f * 1.4426950408889634f; // 32^-0.5 * log2(e)
    const int rwl = warp * 32;
    uint32_t Qh[2][2][4];
    #pragma unroll
    for (int mt = 0; mt < 2; ++mt)
        #pragma unroll
        for (int ch = 0; ch < 2; ++ch)
            #pragma unroll
            for (int pos = 0; pos < 4; ++pos) {
                const int row = half*256 + rwl + mt*16 + g4 + (pos & 1)*8;
                const int d   = ch*16 + 2*t4 + (pos >> 1)*8;
                const int so  = (row >> 3)*64 + (row & 7);
                float f0 = qp[(size_t)d*4096 + so] * qscale;
                float f1 = qp[(size_t)(d+1)*4096 + so] * qscale;
                Qh[mt][ch][pos] = pack16(f16_of(f0), f16_of(f1));
            }

    float O[2][4][4];
    float Lacc[2][4];
    #pragma unroll
    for (int mt = 0; mt < 2; ++mt) {
        #pragma unroll
        for (int e = 0; e < 4; ++e) Lacc[mt][e] = 0.f;
        #pragma unroll
        for (int nt = 0; nt < 4; ++nt)
            #pragma unroll
            for (int e = 0; e < 4; ++e) O[mt][nt][e] = 0.f;
    }
    const uint32_t ONES = 0x3C003C00u;

    __syncthreads();

    // ================= mainloop: 16 tiles of 32 keys =================
    #pragma unroll 1
    for (int kbl = 0; kbl < 512; kbl += 32) {
        // ---- K B-fragments (8x LDS.64) ----
        uint2 Bk[2][4];
        #pragma unroll
        for (int ch = 0; ch < 2; ++ch)
            #pragma unroll
            for (int nt = 0; nt < 4; ++nt) {
                const int key = kbl + nt*8 + g4;
                Bk[ch][nt] = *reinterpret_cast<const uint2*>(
                    smw + OFF_K + key*KP2 + ch*8 + 2*t4);
            }

        // ---- S = Q K^T : f16 accumulate, D packed f16x2 ----
        uint32_t Sh[2][4][2];
        #pragma unroll
        for (int mt = 0; mt < 2; ++mt)
            #pragma unroll
            for (int nt = 0; nt < 4; ++nt) { Sh[mt][nt][0] = 0u; Sh[mt][nt][1] = 0u; }

        #pragma unroll
        for (int ch = 0; ch < 2; ++ch)
            #pragma unroll
            for (int nt = 0; nt < 4; ++nt)
                #pragma unroll
                for (int mt = 0; mt < 2; ++mt)
                    mma16h(Sh[mt][nt], Qh[mt][ch][0],Qh[mt][ch][1],Qh[mt][ch][2],Qh[mt][ch][3],
                           Bk[ch][nt].x, Bk[ch][nt].y);

        // ---- prefetch V B-fragments (hidden under softmax) ----
        uint2 Bv[2][4];
        #pragma unroll
        for (int chk = 0; chk < 2; ++chk)
            #pragma unroll
            for (int ntd = 0; ntd < 4; ++ntd) {
                const int d = ntd*8 + g4;
                Bv[chk][ntd] = *reinterpret_cast<const uint2*>(
                    smw + OFF_V + d*VP2 + (kbl >> 1) + chk*8 + 2*t4);
            }

        // ---- softmax numerators: ex2 directly on packed f16x2 S ----
        uint32_t P[2][4][2];
        #pragma unroll
        for (int mt = 0; mt < 2; ++mt)
            #pragma unroll
            for (int nt = 0; nt < 4; ++nt) {
                P[mt][nt][0] = ex2_f16x2(Sh[mt][nt][0]);
                P[mt][nt][1] = ex2_f16x2(Sh[mt][nt][1]);
            }

        // ---- L += P @ ones (fp32 accum on tensor pipe) ----
        #pragma unroll
        for (int chk = 0; chk < 2; ++chk)
            #pragma unroll
            for (int mt = 0; mt < 2; ++mt)
                mma16(Lacc[mt],
                      P[mt][2*chk][0],   P[mt][2*chk][1],
                      P[mt][2*chk+1][0], P[mt][2*chk+1][1],
                      ONES, ONES);

        // ---- O += P V (fp32 accum) ----
        #pragma unroll
        for (int chk = 0; chk < 2; ++chk)
            #pragma unroll
            for (int ntd = 0; ntd < 4; ++ntd)
                #pragma unroll
                for (int mt = 0; mt < 2; ++mt)
                    mma16(O[mt][ntd],
                          P[mt][2*chk][0],   P[mt][2*chk][1],
                          P[mt][2*chk+1][0], P[mt][2*chk+1][1],
                          Bv[chk][ntd].x, Bv[chk][ntd].y);
    }

    // ---- normalize; repurpose dead K/V smem for Ob + fp32 conv tile ----
    float inv0[2], inv1[2];
    #pragma unroll
    for (int mt = 0; mt < 2; ++mt) {
        inv0[mt] = 1.0f / Lacc[mt][0];
        inv1[mt] = 1.0f / Lacc[mt][2];
    }
    __syncthreads();   // mainloop smem reads complete

    #pragma unroll
    for (int mt = 0; mt < 2; ++mt) {
        const int r = rwl + mt*16 + g4;
        #pragma unroll
        for (int ntd = 0; ntd < 4; ++ntd) {
            const int dd = ntd*8 + 2*t4;
            Ob[r*36 + dd]        = O[mt][ntd][0] * inv0[mt];
            Ob[r*36 + dd + 1]    = O[mt][ntd][1] * inv0[mt];
            Ob[(r+8)*36 + dd]    = O[mt][ntd][2] * inv1[mt];
            Ob[(r+8)*36 + dd +1] = O[mt][ntd][3] * inv1[mt];
        }
    }

    // ---- fill fp32 V conv tile: 34 halo h-rows x 8 w x 32 d, coalesced float4 ----
    const int hstart = half*32 - 1;
    for (int e = tid; e < 34*64; e += THREADS) {
        const int hl  = e >> 6;
        const int rem = e & 63;
        const int d   = rem >> 1;
        const int q   = (rem & 1) * 4;
        const int hh  = hstart + hl;
        if (hh >= 0 && hh < 64) {
            float4 v = *reinterpret_cast<const float4*>(vp + (size_t)d*4096 + hh*64 + q);
            sVf[(hl*8 + q + 0)*36 + d] = v.x;
            sVf[(hl*8 + q + 1)*36 + d] = v.y;
            sVf[(hl*8 + q + 2)*36 + d] = v.z;
            sVf[(hl*8 + q + 3)*36 + d] = v.w;
        }
    }
    __syncthreads();

    // ---- fused rpe depthwise 3x3 from smem (exact fp32) + store ----
    {
        const int lg = half*256 + tid;
        const int h = lg >> 3, wsp = lg & 7;
        float o[32];
        const float4* ob4 = reinterpret_cast<const float4*>(Ob + tid*36);
        #pragma unroll
        for (int i = 0; i < 8; ++i) {
            float4 v = ob4[i];
            o[4*i] = v.x; o[4*i+1] = v.y; o[4*i+2] = v.z; o[4*i+3] = v.w;
        }

        #pragma unroll
        for (int kh = 0; kh < 3; ++kh) {
            const int hh = h + kh - 1;
            if (hh < 0 || hh >= 64) continue;
            const int hl = hh - hstart;
            #pragma unroll
            for (int kw = 0; kw < 3; ++kw) {
                const int ww = wsp + kw - 1;
                if (ww < 0 || ww >= 8) continue;
                const float4* v4 = reinterpret_cast<const float4*>(sVf + (hl*8 + ww)*36);
                const float4* w4 = reinterpret_cast<const float4*>(sWt + (kh*3 + kw)*32);
                #pragma unroll
                for (int i = 0; i < 8; ++i) {
                    float4 vv = v4[i], wv = w4[i];
                    o[4*i]   += wv.x * vv.x;
                    o[4*i+1] += wv.y * vv.y;
                    o[4*i+2] += wv.z * vv.z;
                    o[4*i+3] += wv.w * vv.w;
                }
            }
        }
        #pragma unroll
        for (int d = 0; d < 32; ++d) o[d] += sB[d];

        float4* orow = reinterpret_cast<float4*>(
            out + ((size_t)(b*4096 + h*64 + nw*8 + wsp))*128 + head*32);
        #pragma unroll
        for (int i = 0; i < 8; ++i)
            orow[i] = make_float4(o[4*i], o[4*i+1], o[4*i+2], o[4*i+3]);
    }
}

extern "C" void kernel_launch(void* const* d_in, const int* in_sizes, int n_in,
                              void* d_out, int out_size)
{
    const float* temp   = (const float*)d_in[0];
    const float* conv_w = (const float*)d_in[1];
    const float* conv_b = (const float*)d_in[2];
    float* out = (float*)d_out;

    cudaFuncSetAttribute(cswin_attn_f16v9,
                         cudaFuncAttributeMaxDynamicSharedMemorySize, SMEM_BYTES);
    cswin_attn_f16v9<<<1024, THREADS, SMEM_BYTES>>>(temp, conv_w, conv_b, out);
}

// round 14
// speedup vs baseline: 1.3111x; 1.0041x over previous
#include <cuda_runtime.h>
#include <cstdint>

#define THREADS 256

// ---- smem u32 layout (per CTA; 2 CTAs/SM) ----
#define KP2 24                        // K row stride (u32); conflict-free LDS.64
#define VP2 280                       // V row stride (u32); conflict-free LDS.64
#define OFF_K 0                       // u32[512*KP2]  K f16x2 pairs along d
#define OFF_V (512*KP2)               // u32[32*VP2]   V f16x2 pairs along key
#define OFF_W (OFF_V + 32*VP2)        // f32[288] transposed [tap][d]
#define OFF_B (OFF_W + 288)           // f32[32]
#define SMEM_WORDS (OFF_B + 32)
#define SMEM_BYTES (SMEM_WORDS*4)     // ~86.3 KB -> 2 CTAs co-resident, L1D ~56KB preserved
// epilogue aliases (dead K/V region):
#define OFF_OB 0                      // f32[256*36]  normalized O staging
#define OFF_VF (256*36)               // f32[272*36]  fp32 V conv tile (34 h x 8 w rows)

__device__ __forceinline__ uint16_t f16_of(float f){
    uint16_t u; asm("cvt.rn.f16.f32 %0, %1;" : "=h"(u) : "f"(f)); return u;
}
__device__ __forceinline__ uint32_t pack16(uint16_t lo, uint16_t hi){
    uint32_t d; asm("mov.b32 %0, {%1, %2};" : "=r"(d) : "h"(lo), "h"(hi)); return d;
}
__device__ __forceinline__ uint32_t packf16x2(float lo, float hi){
    uint32_t d; asm("cvt.rn.f16x2.f32 %0, %1, %2;" : "=r"(d) : "f"(hi), "f"(lo)); return d;
}
__device__ __forceinline__ uint32_t ex2_f16x2(uint32_t x){
    uint32_t r; asm("ex2.approx.f16x2 %0, %1;" : "=r"(r) : "r"(x)); return r;
}
// fp32-accum mma (PV + L)
__device__ __forceinline__ void mma16(float* c, uint32_t a0,uint32_t a1,uint32_t a2,uint32_t a3,
                                      uint32_t b0,uint32_t b1){
    asm("mma.sync.aligned.m16n8k16.row.col.f32.f16.f16.f32 "
        "{%0,%1,%2,%3},{%4,%5,%6,%7},{%8,%9},{%0,%1,%2,%3};"
        : "+f"(c[0]),"+f"(c[1]),"+f"(c[2]),"+f"(c[3])
        : "r"(a0),"r"(a1),"r"(a2),"r"(a3),"r"(b0),"r"(b1));
}
// f16-accum mma (QK): D = 2x f16x2 regs, (c0,c1) row g4 / (c2,c3) row g4+8
__device__ __forceinline__ void mma16h(uint32_t* c, uint32_t a0,uint32_t a1,uint32_t a2,uint32_t a3,
                                       uint32_t b0,uint32_t b1){
    asm("mma.sync.aligned.m16n8k16.row.col.f16.f16.f16.f16 "
        "{%0,%1},{%2,%3,%4,%5},{%6,%7},{%0,%1};"
        : "+r"(c[0]),"+r"(c[1])
        : "r"(a0),"r"(a1),"r"(a2),"r"(a3),"r"(b0),"r"(b1));
}
// word position within a 16-word row for logical d-pair dp (pairs (j, j+4) interleaved)
__device__ __forceinline__ int wordpos(int dp){
    return (dp & 8) + ((dp & 3) << 1) + ((dp >> 2) & 1);
}

// QK of tile KBL into SH (f16 accum)  [FIXED: Qh[mt][ch], was Qh[mt][2*ch] OOB]
#define QK_TILE(KBL, SH) do {                                                  \
    uint2 Bk[2][4];                                                            \
    _Pragma("unroll")                                                          \
    for (int ch = 0; ch < 2; ++ch)                                             \
        _Pragma("unroll")                                                      \
        for (int nt = 0; nt < 4; ++nt) {                                       \
            const int key = (KBL) + nt*8 + g4;                                 \
            Bk[ch][nt] = *reinterpret_cast<const uint2*>(                      \
                smw + OFF_K + key*KP2 + ch*8 + 2*t4);                          \
        }                                                                      \
    _Pragma("unroll")                                                          \
    for (int mt = 0; mt < 2; ++mt)                                             \
        _Pragma("unroll")                                                      \
        for (int nt = 0; nt < 4; ++nt) { SH[mt][nt][0] = 0u; SH[mt][nt][1] = 0u; } \
    _Pragma("unroll")                                                          \
    for (int ch = 0; ch < 2; ++ch)                                             \
        _Pragma("unroll")                                                      \
        for (int nt = 0; nt < 4; ++nt)                                         \
            _Pragma("unroll")                                                  \
            for (int mt = 0; mt < 2; ++mt)                                     \
                mma16h(SH[mt][nt], Qh[mt][ch][0],Qh[mt][ch][1],                \
                       Qh[mt][ch][2],Qh[mt][ch][3],                            \
                       Bk[ch][nt].x, Bk[ch][nt].y);                            \
} while (0)

// One pipelined step: P=ex2(SCUR) [MUFU] ; QK(KBL+32)->SNXT [tensor, overlaps]
// ; then Bv, L, PV of tile KBL with P.
#define STEP(KBL, SCUR, SNXT) do {                                             \
    uint32_t P[2][4][2];                                                       \
    _Pragma("unroll")                                                          \
    for (int mt = 0; mt < 2; ++mt)                                             \
        _Pragma("unroll")                                                      \
        for (int nt = 0; nt < 4; ++nt) {                                       \
            P[mt][nt][0] = ex2_f16x2(SCUR[mt][nt][0]);                         \
            P[mt][nt][1] = ex2_f16x2(SCUR[mt][nt][1]);                         \
        }                                                                      \
    const int nkbl = ((KBL) + 32) & 511;                                       \
    QK_TILE(nkbl, SNXT);                                                       \
    uint2 Bv[2][4];                                                            \
    _Pragma("unroll")                                                          \
    for (int chk = 0; chk < 2; ++chk)                                          \
        _Pragma("unroll")                                                      \
        for (int ntd = 0; ntd < 4; ++ntd) {                                    \
            const int d = ntd*8 + g4;                                          \
            Bv[chk][ntd] = *reinterpret_cast<const uint2*>(                    \
                smw + OFF_V + d*VP2 + ((KBL) >> 1) + chk*8 + 2*t4);            \
        }                                                                      \
    _Pragma("unroll")                                                          \
    for (int chk = 0; chk < 2; ++chk)                                          \
        _Pragma("unroll")                                                      \
        for (int mt = 0; mt < 2; ++mt)                                         \
            mma16(Lacc[mt],                                                    \
                  P[mt][2*chk][0],   P[mt][2*chk][1],                          \
                  P[mt][2*chk+1][0], P[mt][2*chk+1][1],                        \
                  ONES, ONES);                                                 \
    _Pragma("unroll")                                                          \
    for (int chk = 0; chk < 2; ++chk)                                          \
        _Pragma("unroll")                                                      \
        for (int ntd = 0; ntd < 4; ++ntd)                                      \
            _Pragma("unroll")                                                  \
            for (int mt = 0; mt < 2; ++mt)                                     \
                mma16(O[mt][ntd],                                              \
                      P[mt][2*chk][0],   P[mt][2*chk][1],                      \
                      P[mt][2*chk+1][0], P[mt][2*chk+1][1],                    \
                      Bv[chk][ntd].x, Bv[chk][ntd].y);                         \
} while (0)

// 2 CTAs per (window, head); each CTA owns 256 query rows, holds full K/V.
__global__ void __launch_bounds__(THREADS, 2)
cswin_attn_f16v11(const float* __restrict__ temp,
                  const float* __restrict__ conv_w,
                  const float* __restrict__ conv_b,
                  float* __restrict__ out)
{
    extern __shared__ uint32_t smw[];
    float* sWt = (float*)(smw + OFF_W);
    float* sB  = (float*)(smw + OFF_B);
    float* Ob  = (float*)(smw + OFF_OB);
    float* sVf = (float*)(smw + OFF_VF);

    const int tid  = threadIdx.x;
    const int lane = tid & 31;
    const int warp = tid >> 5;
    const int g4   = lane >> 2;
    const int t4   = lane & 3;

    const int bid   = blockIdx.x;
    const int half  = bid & 1;
    const int whead = bid >> 1;
    const int head  = whead & 3;
    const int w     = whead >> 2;
    const int b     = w >> 3;
    const int nw    = w & 7;

    const size_t planeStride = 128ull * 4096ull;
    const float* qp = temp + ((size_t)b*3 + 0)*planeStride + (size_t)(head*32)*4096 + nw*8;
    const float* kp = temp + ((size_t)b*3 + 1)*planeStride + (size_t)(head*32)*4096 + nw*8;
    const float* vp = temp + ((size_t)b*3 + 2)*planeStride + (size_t)(head*32)*4096 + nw*8;

    // ---- K fill: lane-quad-rotated d order (coalesced LDG, ~2-way STS) ----
    {
        const int key0 = 2*tid;
        const int so = (key0 >> 3)*64 + (key0 & 7);
        #pragma unroll
        for (int s = 0; s < 16; ++s) {
            const int dp = (s + g4) & 15;
            const int d0 = 2*dp;
            float2 v0 = *reinterpret_cast<const float2*>(kp + (size_t)d0*4096 + so);
            float2 v1 = *reinterpret_cast<const float2*>(kp + (size_t)(d0+1)*4096 + so);
            const int wp = wordpos(dp);
            smw[OFF_K + key0*KP2 + wp]     = pack16(f16_of(v0.x), f16_of(v1.x));
            smw[OFF_K + (key0+1)*KP2 + wp] = pack16(f16_of(v0.y), f16_of(v1.y));
        }
    }
    // ---- V fill: f16 pairs along key, (t4, t4+4) word-interleaved ----
    for (int i = tid; i < 32*256; i += THREADS) {
        const int d = i >> 8, kpi = i & 255;
        const int t = kpi & 7, m = kpi >> 3;
        const int word = m*8 + ((t < 4) ? 2*t : 2*(t-4) + 1);
        const int key0 = 2*kpi;
        const int so = (key0 >> 3)*64 + (key0 & 7);
        float2 v = *reinterpret_cast<const float2*>(vp + (size_t)d*4096 + so);
        smw[OFF_V + d*VP2 + word] = packf16x2(v.x, v.y);
    }
    for (int i = tid; i < 288; i += THREADS) {
        const int d = i / 9, widx = i % 9;
        sWt[widx*32 + d] = conv_w[head*288 + i];
    }
    if (tid < 32) sB[tid] = conv_b[head*32 + tid];

    // ---- Q fragments -> registers (single f16, scale folded) ----
    const float qscale = 0.17677669529663687f * 1.4426950408889634f; // 32^-0.5 * log2(e)
    const int rwl = warp * 32;
    uint32_t Qh[2][2][4];
    #pragma unroll
    for (int mt = 0; mt < 2; ++mt)
        #pragma unroll
        for (int ch = 0; ch < 2; ++ch)
            #pragma unroll
            for (int pos = 0; pos < 4; ++pos) {
                const int row = half*256 + rwl + mt*16 + g4 + (pos & 1)*8;
                const int d   = ch*16 + 2*t4 + (pos >> 1)*8;
                const int so  = (row >> 3)*64 + (row & 7);
                float f0 = qp[(size_t)d*4096 + so] * qscale;
                float f1 = qp[(size_t)(d+1)*4096 + so] * qscale;
                Qh[mt][ch][pos] = pack16(f16_of(f0), f16_of(f1));
            }

    float O[2][4][4];
    float Lacc[2][4];
    #pragma unroll
    for (int mt = 0; mt < 2; ++mt) {
        #pragma unroll
        for (int e = 0; e < 4; ++e) Lacc[mt][e] = 0.f;
        #pragma unroll
        for (int nt = 0; nt < 4; ++nt)
            #pragma unroll
            for (int e = 0; e < 4; ++e) O[mt][nt][e] = 0.f;
    }
    const uint32_t ONES = 0x3C003C00u;

    __syncthreads();

    // ====== mainloop: 16 tiles, compute-phase software pipeline ======
    uint32_t ShA[2][4][2], ShB[2][4][2];
    QK_TILE(0, ShA);
    #pragma unroll 1
    for (int kbl = 0; kbl < 512; kbl += 64) {
        STEP(kbl,      ShA, ShB);
        STEP(kbl + 32, ShB, ShA);   // last iter: QK(0) recomputed into ShA, unused
    }

    // ---- normalize; repurpose dead K/V smem for Ob + fp32 conv tile ----
    float inv0[2], inv1[2];
    #pragma unroll
    for (int mt = 0; mt < 2; ++mt) {
        inv0[mt] = 1.0f / Lacc[mt][0];
        inv1[mt] = 1.0f / Lacc[mt][2];
    }
    __syncthreads();   // mainloop smem reads complete

    #pragma unroll
    for (int mt = 0; mt < 2; ++mt) {
        const int r = rwl + mt*16 + g4;
        #pragma unroll
        for (int ntd = 0; ntd < 4; ++ntd) {
            const int dd = ntd*8 + 2*t4;
            Ob[r*36 + dd]        = O[mt][ntd][0] * inv0[mt];
            Ob[r*36 + dd + 1]    = O[mt][ntd][1] * inv0[mt];
            Ob[(r+8)*36 + dd]    = O[mt][ntd][2] * inv1[mt];
            Ob[(r+8)*36 + dd +1] = O[mt][ntd][3] * inv1[mt];
        }
    }

    // ---- fill fp32 V conv tile: 34 halo h-rows x 8 w x 32 d, coalesced float4 ----
    const int hstart = half*32 - 1;
    for (int e = tid; e < 34*64; e += THREADS) {
        const int hl  = e >> 6;
        const int rem = e & 63;
        const int d   = rem >> 1;
        const int q   = (rem & 1) * 4;
        const int hh  = hstart + hl;
        if (hh >= 0 && hh < 64) {
            float4 v = *reinterpret_cast<const float4*>(vp + (size_t)d*4096 + hh*64 + q);
            sVf[(hl*8 + q + 0)*36 + d] = v.x;
            sVf[(hl*8 + q + 1)*36 + d] = v.y;
            sVf[(hl*8 + q + 2)*36 + d] = v.z;
            sVf[(hl*8 + q + 3)*36 + d] = v.w;
        }
    }
    __syncthreads();

    // ---- fused rpe depthwise 3x3 from smem (exact fp32) + store ----
    {
        const int lg = half*256 + tid;
        const int h = lg >> 3, wsp = lg & 7;
        float o[32];
        const float4* ob4 = reinterpret_cast<const float4*>(Ob + tid*36);
        #pragma unroll
        for (int i = 0; i < 8; ++i) {
            float4 v = ob4[i];
            o[4*i] = v.x; o[4*i+1] = v.y; o[4*i+2] = v.z; o[4*i+3] = v.w;
        }

        #pragma unroll
        for (int kh = 0; kh < 3; ++kh) {
            const int hh = h + kh - 1;
            if (hh < 0 || hh >= 64) continue;
            const int hl = hh - hstart;
            #pragma unroll
            for (int kw = 0; kw < 3; ++kw) {
                const int ww = wsp + kw - 1;
                if (ww < 0 || ww >= 8) continue;
                const float4* v4 = reinterpret_cast<const float4*>(sVf + (hl*8 + ww)*36);
                const float4* w4 = reinterpret_cast<const float4*>(sWt + (kh*3 + kw)*32);
                #pragma unroll
                for (int i = 0; i < 8; ++i) {
                    float4 vv = v4[i], wv = w4[i];
                    o[4*i]   += wv.x * vv.x;
                    o[4*i+1] += wv.y * vv.y;
                    o[4*i+2] += wv.z * vv.z;
                    o[4*i+3] += wv.w * vv.w;
                }
            }
        }
        #pragma unroll
        for (int d = 0; d < 32; ++d) o[d] += sB[d];

        float4* orow = reinterpret_cast<float4*>(
            out + ((size_t)(b*4096 + h*64 + nw*8 + wsp))*128 + head*32);
        #pragma unroll
        for (int i = 0; i < 8; ++i)
            orow[i] = make_float4(o[4*i], o[4*i+1], o[4*i+2], o[4*i+3]);
    }
}

extern "C" void kernel_launch(void* const* d_in, const int* in_sizes, int n_in,
                              void* d_out, int out_size)
{
    const float* temp   = (const float*)d_in[0];
    const float* conv_w = (const float*)d_in[1];
    const float* conv_b = (const float*)d_in[2];
    float* out = (float*)d_out;

    cudaFuncSetAttribute(cswin_attn_f16v11,
                         cudaFuncAttributeMaxDynamicSharedMemorySize, SMEM_BYTES);
    cswin_attn_f16v11<<<1024, THREADS, SMEM_BYTES>>>(temp, conv_w, conv_b, out);
}

// round 16
// speedup vs baseline: 1.3323x; 1.0162x over previous
#include <cuda_runtime.h>
#include <cstdint>

#define THREADS 512

// ---- smem u32 layout (per CTA; 2 CTAs/SM) ----
#define KP2 24                        // K row stride (u32); conflict-free LDS.64
#define VP2 280                       // V row stride (u32); conflict-free LDS.64
#define OFF_K 0                       // u32[512*KP2]  K f16x2 pairs along d
#define OFF_V (512*KP2)               // u32[32*VP2]   V f16x2 pairs along key
#define OFF_W (OFF_V + 32*VP2)        // f32[288] transposed [tap][d]
#define OFF_B (OFF_W + 288)           // f32[32]
#define SMEM_WORDS (OFF_B + 32)
#define SMEM_BYTES (SMEM_WORDS*4)     // ~86.3 KB -> 2 CTAs co-resident, L1D ~56KB preserved
// epilogue aliases (dead K/V region):
#define OFF_OB 0                      // f32[256*36]  normalized O staging
#define OFF_VF (256*36)               // f32[272*36]  fp32 V conv tile (34 h x 8 w rows)

__device__ __forceinline__ uint16_t f16_of(float f){
    uint16_t u; asm("cvt.rn.f16.f32 %0, %1;" : "=h"(u) : "f"(f)); return u;
}
__device__ __forceinline__ uint32_t pack16(uint16_t lo, uint16_t hi){
    uint32_t d; asm("mov.b32 %0, {%1, %2};" : "=r"(d) : "h"(lo), "h"(hi)); return d;
}
__device__ __forceinline__ uint32_t packf16x2(float lo, float hi){
    uint32_t d; asm("cvt.rn.f16x2.f32 %0, %1, %2;" : "=r"(d) : "f"(hi), "f"(lo)); return d;
}
__device__ __forceinline__ uint32_t ex2_f16x2(uint32_t x){
    uint32_t r; asm("ex2.approx.f16x2 %0, %1;" : "=r"(r) : "r"(x)); return r;
}
// fp32-accum mma (PV + L)
__device__ __forceinline__ void mma16(float* c, uint32_t a0,uint32_t a1,uint32_t a2,uint32_t a3,
                                      uint32_t b0,uint32_t b1){
    asm("mma.sync.aligned.m16n8k16.row.col.f32.f16.f16.f32 "
        "{%0,%1,%2,%3},{%4,%5,%6,%7},{%8,%9},{%0,%1,%2,%3};"
        : "+f"(c[0]),"+f"(c[1]),"+f"(c[2]),"+f"(c[3])
        : "r"(a0),"r"(a1),"r"(a2),"r"(a3),"r"(b0),"r"(b1));
}
// f16-accum mma (QK): D = 2x f16x2 regs, (c0,c1) row g4 / (c2,c3) row g4+8
__device__ __forceinline__ void mma16h(uint32_t* c, uint32_t a0,uint32_t a1,uint32_t a2,uint32_t a3,
                                       uint32_t b0,uint32_t b1){
    asm("mma.sync.aligned.m16n8k16.row.col.f16.f16.f16.f16 "
        "{%0,%1},{%2,%3,%4,%5},{%6,%7},{%0,%1};"
        : "+r"(c[0]),"+r"(c[1])
        : "r"(a0),"r"(a1),"r"(a2),"r"(a3),"r"(b0),"r"(b1));
}
// word position within a 16-word row for logical d-pair dp (pairs (j, j+4) interleaved)
__device__ __forceinline__ int wordpos(int dp){
    return (dp & 8) + ((dp & 3) << 1) + ((dp >> 2) & 1);
}

// 2 CTAs per (window, head); 512 threads; 16 warps x 16 query rows each.
// 32 warps/SM (2 CTAs) at <=64 regs: double the latency hiding of the 126-reg version.
__global__ void __launch_bounds__(THREADS, 2)
cswin_attn_f16v12(const float* __restrict__ temp,
                  const float* __restrict__ conv_w,
                  const float* __restrict__ conv_b,
                  float* __restrict__ out)
{
    extern __shared__ uint32_t smw[];
    float* sWt = (float*)(smw + OFF_W);
    float* sB  = (float*)(smw + OFF_B);
    float* Ob  = (float*)(smw + OFF_OB);
    float* sVf = (float*)(smw + OFF_VF);

    const int tid  = threadIdx.x;
    const int lane = tid & 31;
    const int warp = tid >> 5;
    const int g4   = lane >> 2;
    const int t4   = lane & 3;

    const int bid   = blockIdx.x;
    const int half  = bid & 1;
    const int whead = bid >> 1;
    const int head  = whead & 3;
    const int w     = whead >> 2;
    const int b     = w >> 3;
    const int nw    = w & 7;

    const size_t planeStride = 128ull * 4096ull;
    const float* qp = temp + ((size_t)b*3 + 0)*planeStride + (size_t)(head*32)*4096 + nw*8;
    const float* kp = temp + ((size_t)b*3 + 1)*planeStride + (size_t)(head*32)*4096 + nw*8;
    const float* vp = temp + ((size_t)b*3 + 2)*planeStride + (size_t)(head*32)*4096 + nw*8;

    // ---- parallel fills: warps 0-7 fill K, warps 8-15 fill V ----
    if (warp < 8) {
        // K: thread owns even key pair; lane-quad-rotated d order (coalesced LDG, ~2-way STS)
        const int key0 = 2*tid;            // tid in [0,256)
        const int so = (key0 >> 3)*64 + (key0 & 7);
        #pragma unroll
        for (int s = 0; s < 16; ++s) {
            const int dp = (s + g4) & 15;
            const int d0 = 2*dp;
            float2 v0 = *reinterpret_cast<const float2*>(kp + (size_t)d0*4096 + so);
            float2 v1 = *reinterpret_cast<const float2*>(kp + (size_t)(d0+1)*4096 + so);
            const int wp = wordpos(dp);
            smw[OFF_K + key0*KP2 + wp]     = pack16(f16_of(v0.x), f16_of(v1.x));
            smw[OFF_K + (key0+1)*KP2 + wp] = pack16(f16_of(v0.y), f16_of(v1.y));
        }
    } else {
        // V: f16 pairs along key, (t4, t4+4) word-interleaved
        for (int i = tid - 256; i < 32*256; i += 256) {
            const int d = i >> 8, kpi = i & 255;
            const int t = kpi & 7, m = kpi >> 3;
            const int word = m*8 + ((t < 4) ? 2*t : 2*(t-4) + 1);
            const int key0 = 2*kpi;
            const int so = (key0 >> 3)*64 + (key0 & 7);
            float2 v = *reinterpret_cast<const float2*>(vp + (size_t)d*4096 + so);
            smw[OFF_V + d*VP2 + word] = packf16x2(v.x, v.y);
        }
    }
    if (tid < 288) {
        const int d = tid / 9, widx = tid % 9;
        sWt[widx*32 + d] = conv_w[head*288 + tid];
    }
    if (tid >= 480) sB[tid - 480] = conv_b[head*32 + (tid - 480)];

    // ---- Q fragments -> registers (single f16, scale folded); m16 tile ----
    const float qscale = 0.17677669529663687f * 1.4426950408889634f; // 32^-0.5 * log2(e)
    const int rwl = warp * 16;
    uint32_t Qh[2][4];
    #pragma unroll
    for (int ch = 0; ch < 2; ++ch)
        #pragma unroll
        for (int pos = 0; pos < 4; ++pos) {
            const int row = half*256 + rwl + g4 + (pos & 1)*8;
            const int d   = ch*16 + 2*t4 + (pos >> 1)*8;
            const int so  = (row >> 3)*64 + (row & 7);
            float f0 = qp[(size_t)d*4096 + so] * qscale;
            float f1 = qp[(size_t)(d+1)*4096 + so] * qscale;
            Qh[ch][pos] = pack16(f16_of(f0), f16_of(f1));
        }

    float O[4][4];
    float Lacc[4];
    #pragma unroll
    for (int e = 0; e < 4; ++e) Lacc[e] = 0.f;
    #pragma unroll
    for (int nt = 0; nt < 4; ++nt)
        #pragma unroll
        for (int e = 0; e < 4; ++e) O[nt][e] = 0.f;
    const uint32_t ONES = 0x3C003C00u;

    __syncthreads();

    // ================= mainloop: 16 tiles of 32 keys =================
    #pragma unroll 1
    for (int kbl = 0; kbl < 512; kbl += 32) {
        // ---- S = Q K^T : f16 accumulate, D packed f16x2; B loaded per-ch ----
        uint32_t Sh[4][2];
        #pragma unroll
        for (int nt = 0; nt < 4; ++nt) { Sh[nt][0] = 0u; Sh[nt][1] = 0u; }

        #pragma unroll
        for (int ch = 0; ch < 2; ++ch) {
            uint2 Bk[4];
            #pragma unroll
            for (int nt = 0; nt < 4; ++nt) {
                const int key = kbl + nt*8 + g4;
                Bk[nt] = *reinterpret_cast<const uint2*>(
                    smw + OFF_K + key*KP2 + ch*8 + 2*t4);
            }
            #pragma unroll
            for (int nt = 0; nt < 4; ++nt)
                mma16h(Sh[nt], Qh[ch][0],Qh[ch][1],Qh[ch][2],Qh[ch][3],
                       Bk[nt].x, Bk[nt].y);
        }

        // ---- softmax numerators: ex2 on packed f16x2 S (in place -> P) ----
        uint32_t P[4][2];
        #pragma unroll
        for (int nt = 0; nt < 4; ++nt) {
            P[nt][0] = ex2_f16x2(Sh[nt][0]);
            P[nt][1] = ex2_f16x2(Sh[nt][1]);
        }

        // ---- L and O accumulation, B(V) loaded per-chunk ----
        #pragma unroll
        for (int chk = 0; chk < 2; ++chk) {
            mma16(Lacc,
                  P[2*chk][0],   P[2*chk][1],
                  P[2*chk+1][0], P[2*chk+1][1],
                  ONES, ONES);
            uint2 Bv[4];
            #pragma unroll
            for (int ntd = 0; ntd < 4; ++ntd) {
                const int d = ntd*8 + g4;
                Bv[ntd] = *reinterpret_cast<const uint2*>(
                    smw + OFF_V + d*VP2 + (kbl >> 1) + chk*8 + 2*t4);
            }
            #pragma unroll
            for (int ntd = 0; ntd < 4; ++ntd)
                mma16(O[ntd],
                      P[2*chk][0],   P[2*chk][1],
                      P[2*chk+1][0], P[2*chk+1][1],
                      Bv[ntd].x, Bv[ntd].y);
        }
    }

    // ---- normalize; repurpose dead K/V smem for Ob + fp32 conv tile ----
    const float inv0 = 1.0f / Lacc[0];   // row g4
    const float inv1 = 1.0f / Lacc[2];   // row g4+8
    __syncthreads();   // mainloop smem reads complete

    {
        const int r = rwl + g4;
        #pragma unroll
        for (int ntd = 0; ntd < 4; ++ntd) {
            const int dd = ntd*8 + 2*t4;
            Ob[r*36 + dd]        = O[ntd][0] * inv0;
            Ob[r*36 + dd + 1]    = O[ntd][1] * inv0;
            Ob[(r+8)*36 + dd]    = O[ntd][2] * inv1;
            Ob[(r+8)*36 + dd +1] = O[ntd][3] * inv1;
        }
    }

    // ---- fill fp32 V conv tile: 34 halo h-rows x 8 w x 32 d, coalesced float4 ----
    const int hstart = half*32 - 1;
    for (int e = tid; e < 34*64; e += THREADS) {
        const int hl  = e >> 6;
        const int rem = e & 63;
        const int d   = rem >> 1;
        const int q   = (rem & 1) * 4;
        const int hh  = hstart + hl;
        if (hh >= 0 && hh < 64) {
            float4 v = *reinterpret_cast<const float4*>(vp + (size_t)d*4096 + hh*64 + q);
            sVf[(hl*8 + q + 0)*36 + d] = v.x;
            sVf[(hl*8 + q + 1)*36 + d] = v.y;
            sVf[(hl*8 + q + 2)*36 + d] = v.z;
            sVf[(hl*8 + q + 3)*36 + d] = v.w;
        }
    }
    __syncthreads();

    // ---- fused rpe depthwise 3x3 from smem (exact fp32) + store ----
    // 2 threads per row: tid>>1 = row, tid&1 = d-half (16 channels each)
    {
        const int rl = tid >> 1;
        const int dh = tid & 1;
        const int lg = half*256 + rl;
        const int h = lg >> 3, wsp = lg & 7;
        float o[16];
        const float4* ob4 = reinterpret_cast<const float4*>(Ob + rl*36 + dh*16);
        #pragma unroll
        for (int i = 0; i < 4; ++i) {
            float4 v = ob4[i];
            o[4*i] = v.x; o[4*i+1] = v.y; o[4*i+2] = v.z; o[4*i+3] = v.w;
        }

        #pragma unroll
        for (int kh = 0; kh < 3; ++kh) {
            const int hh = h + kh - 1;
            if (hh < 0 || hh >= 64) continue;
            const int hl = hh - hstart;
            #pragma unroll
            for (int kw = 0; kw < 3; ++kw) {
                const int ww = wsp + kw - 1;
                if (ww < 0 || ww >= 8) continue;
                const float4* v4 = reinterpret_cast<const float4*>(sVf + (hl*8 + ww)*36 + dh*16);
                const float4* w4 = reinterpret_cast<const float4*>(sWt + (kh*3 + kw)*32 + dh*16);
                #pragma unroll
                for (int i = 0; i < 4; ++i) {
                    float4 vv = v4[i], wv = w4[i];
                    o[4*i]   += wv.x * vv.x;
                    o[4*i+1] += wv.y * vv.y;
                    o[4*i+2] += wv.z * vv.z;
                    o[4*i+3] += wv.w * vv.w;
                }
            }
        }
        #pragma unroll
        for (int d = 0; d < 16; ++d) o[d] += sB[dh*16 + d];

        float4* orow = reinterpret_cast<float4*>(
            out + ((size_t)(b*4096 + h*64 + nw*8 + wsp))*128 + head*32 + dh*16);
        #pragma unroll
        for (int i = 0; i < 4; ++i)
            orow[i] = make_float4(o[4*i], o[4*i+1], o[4*i+2], o[4*i+3]);
    }
}

extern "C" void kernel_launch(void* const* d_in, const int* in_sizes, int n_in,
                              void* d_out, int out_size)
{
    const float* temp   = (const float*)d_in[0];
    const float* conv_w = (const float*)d_in[1];
    const float* conv_b = (const float*)d_in[2];
    float* out = (float*)d_out;

    cudaFuncSetAttribute(cswin_attn_f16v12,
                         cudaFuncAttributeMaxDynamicSharedMemorySize, SMEM_BYTES);
    cswin_attn_f16v12<<<1024, THREADS, SMEM_BYTES>>>(temp, conv_w, conv_b, out);
}